// round 3
// baseline (speedup 1.0000x reference)
#include <cuda_runtime.h>
#include <math.h>
#include <cstdint>

// Output = 2*PE broadcast: 256 MB pure stores. Pattern period 4 KB.
// Hybrid writer: even-role CTAs push 32 KB chunks through cp.async.bulk
// (TMA/bulk engine), odd-role CTAs write their chunks with st.global.cs
// STG.128 (LSU path). Both engines run concurrently to test whether the
// ~5 TB/s plateau is a per-engine queue limit or the DRAM write ceiling.

#define CHUNK_BYTES   32768
#define CHUNK_FLOAT4  (CHUNK_BYTES / 16)   // 2048

__device__ __forceinline__ void stg_cs_v4(float4* p, float4 v) {
    asm volatile("st.global.cs.v4.f32 [%0], {%1,%2,%3,%4};"
                 :: "l"(p), "f"(v.x), "f"(v.y), "f"(v.z), "f"(v.w) : "memory");
}

__global__ void __launch_bounds__(256)
pe_hybrid_kernel(float* __restrict__ out, long long n_chunks) {
    __shared__ __align__(128) float4 smem[CHUNK_FLOAT4];   // 32 KB

    const int t = threadIdx.x;      // float4 index within 256-float4 period
    const int pos = t >> 2;
    const int c0  = (t & 3) * 4;

    float4 v;
    {
        const float ln1e4_over8 = 1.1512925464970229f;  // ln(10000)/8
        float vals[4];
        #pragma unroll
        for (int k = 0; k < 4; ++k) {
            int c = c0 + k;
            float div = (float)pos * expf(-(float)c * ln1e4_over8);
            float s, co;
            sincosf(div, &s, &co);
            vals[k] = 2.0f * ((c & 1) == 0 ? s : co);
        }
        v.x = vals[0]; v.y = vals[1]; v.z = vals[2]; v.w = vals[3];
    }

    const int role  = blockIdx.x & 1;            // 0 = TMA bulk, 1 = STG
    const long long r     = blockIdx.x >> 1;     // index within role
    const long long nRole = gridDim.x >> 1;

    if (role == 0) {
        // Stage one 32 KB repetition of the pattern.
        #pragma unroll
        for (int p = 0; p < 8; ++p)
            smem[p * 256 + t] = v;
        __syncthreads();

        if (t == 0) {
            asm volatile("fence.proxy.async.shared::cta;" ::: "memory");
            uint32_t s_addr;
            asm("{ .reg .u64 a; cvta.to.shared.u64 a, %1; cvt.u32.u64 %0, a; }"
                : "=r"(s_addr) : "l"(smem));
            // Even chunk ids: c = 2*i
            for (long long i = r; i * 2 < n_chunks; i += nRole) {
                const char* dst = (const char*)out + (i * 2) * (long long)CHUNK_BYTES;
                asm volatile(
                    "cp.async.bulk.global.shared::cta.bulk_group [%0], [%1], %2;"
                    :: "l"(dst), "r"(s_addr), "n"(CHUNK_BYTES) : "memory");
            }
            asm volatile("cp.async.bulk.commit_group;" ::: "memory");
            asm volatile("cp.async.bulk.wait_group 0;" ::: "memory");
        }
    } else {
        // Odd chunk ids: c = 2*i + 1. Each chunk = 2048 float4 = 8 per thread.
        for (long long i = r; i * 2 + 1 < n_chunks; i += nRole) {
            float4* base = (float4*)out + (i * 2 + 1) * (long long)CHUNK_FLOAT4;
            #pragma unroll
            for (int p = 0; p < 8; ++p)
                stg_cs_v4(base + p * 256 + t, v);
        }
    }
}

// Tail (not expected for this shape; 256 MB is chunk-divisible).
__global__ void pe_tail_kernel(float* __restrict__ out,
                               long long start_f, long long total_f) {
    long long i = start_f + blockIdx.x * 256LL + threadIdx.x;
    if (i >= total_f) return;
    const float ln1e4_over8 = 1.1512925464970229f;
    int rr = (int)(i & 1023);
    int pos = rr >> 4;
    int c = rr & 15;
    float div = (float)pos * expf(-(float)c * ln1e4_over8);
    float s, co;
    sincosf(div, &s, &co);
    out[i] = 2.0f * ((c & 1) == 0 ? s : co);
}

extern "C" void kernel_launch(void* const* d_in, const int* in_sizes, int n_in,
                              void* d_out, int out_size) {
    (void)d_in; (void)in_sizes; (void)n_in;
    long long total_bytes = (long long)out_size * 4;
    long long n_chunks = total_bytes / CHUNK_BYTES;      // 8192
    long long rem_bytes = total_bytes - n_chunks * CHUNK_BYTES;

    if (n_chunks > 0) {
        // 1184 CTAs = 8/SM; even half drives bulk engine, odd half drives LSU.
        int grid = 1184;
        if ((long long)grid > n_chunks * 2) grid = (int)(n_chunks * 2);
        pe_hybrid_kernel<<<grid, 256>>>((float*)d_out, n_chunks);
    }
    if (rem_bytes > 0) {
        long long start_f = n_chunks * (CHUNK_BYTES / 4);
        long long rem_f = rem_bytes / 4;
        int blocks = (int)((rem_f + 255) / 256);
        pe_tail_kernel<<<blocks, 256>>>((float*)d_out, start_f, (long long)out_size);
    }
}